// round 3
// baseline (speedup 1.0000x reference)
#include <cuda_runtime.h>

// APMLSparse: x[B,N,3], y[B,M,3] fp32 -> scalar loss. B=4, N=M=4096.
//
// Per row n: d_j = sqrt(max(||x_n-y_j||^2,1e-12)), e_j = exp(-d_j), Z = sum e_j.
// Kept = d-ascending prefix while exclusive cumulative mass < 0.8*Z (incl.
// crossing entry, and p>1e-10 filter). loss += sum_kept e_j*d_j / Z.
//
// R2 design: NO per-element histogram atomics (R1's bottleneck: 67M shared
// atomics @2cyc/lane = ~906K LSU cycles/SM-chip, matching 460us).
// Instead: (d,e) stored once as float2 in shared; weighted-quantile threshold
// found by 5 rounds of two-threshold trisection (pure LDS+ALU + one 3-float
// block reduce per round; interval shrinks 243x). Elements in the final tiny
// interval (~100) get exact O(k^2) rank resolution.

#define NTHREADS 256
#define RPC      8
#define MPTS     4096
#define NPT      16           // MPTS / NTHREADS
#define CAP      1024
#define NITER    5

__global__ void apml_zero_out(float* o) { o[0] = 0.0f; }

__global__ __launch_bounds__(NTHREADS, 2)
void apml_kernel(const float* __restrict__ x, const float* __restrict__ y,
                 float* __restrict__ out)
{
    __shared__ float2 de[MPTS];        // 32 KB: (d, e) per element of this row
    __shared__ float  listD[CAP];      // 4 KB
    __shared__ float  listE[CAP];      // 4 KB
    __shared__ float  warpRed[24];     // 3 values x 8 warps
    __shared__ float  s_ctl[4];        // lo, hi, mLo, Z
    __shared__ int    s_cnt;

    const int tid  = threadIdx.x;
    const int lane = tid & 31;
    const int wid  = tid >> 5;

    const int chunksPerBatch = MPTS / RPC;             // 512
    const int b       = blockIdx.x / chunksPerBatch;
    const int rowBase = (blockIdx.x % chunksPerBatch) * RPC;

    // This thread's 16 y points live in registers, reused across RPC rows.
    float yx[NPT], yy[NPT], yz[NPT];
    const float* yb = y + (size_t)b * MPTS * 3;
    #pragma unroll
    for (int k = 0; k < NPT; k++) {
        int j = k * NTHREADS + tid;
        yx[k] = yb[j * 3 + 0];
        yy[k] = yb[j * 3 + 1];
        yz[k] = yb[j * 3 + 2];
    }

    float ctaAcc = 0.0f;

    for (int r = 0; r < RPC; r++) {
        const float* xp = x + ((size_t)b * MPTS + rowBase + r) * 3;
        const float x0 = __ldg(xp + 0);
        const float x1 = __ldg(xp + 1);
        const float x2 = __ldg(xp + 2);

        if (tid == 0) s_cnt = 0;

        // ---- pass 1: d, e -> shared; Z partial in regs ----
        float zp = 0.0f;
        #pragma unroll
        for (int k = 0; k < NPT; k++) {
            float dx = x0 - yx[k];
            float dy = x1 - yy[k];
            float dz = x2 - yz[k];
            float sq = fmaf(dx, dx, fmaf(dy, dy, dz * dz));
            sq = fmaxf(sq, 1e-12f);
            float d = sq * rsqrtf(sq);        // sqrt via MUFU.RSQ + FMUL
            float e = __expf(-d);             // FMUL + MUFU.EX2
            zp += e;
            de[k * NTHREADS + tid] = make_float2(d, e);
        }
        __syncthreads();

        // ---- trisection: find lo<=d*<hi with mass(lo)<T<=mass(hi) ----
        float lo = 0.0f, hi = 16.0f, mLo = 0.0f, Z = 0.0f;
        for (int it = 0; it < NITER; it++) {
            float w  = (hi - lo) * (1.0f / 3.0f);
            float t1 = lo + w;
            float t2 = lo + 2.0f * w;
            float p1 = 0.0f, p2 = 0.0f;
            #pragma unroll
            for (int k = 0; k < NPT; k++) {
                float2 v = de[k * NTHREADS + tid];
                float s2 = (v.x < t2) ? v.y : 0.0f;   // d<t1 implies d<t2
                p2 += s2;
                p1 += (v.x < t1) ? s2 : 0.0f;
            }
            // block reduce (p1, p2, zp)  [zp only meaningful on it==0]
            float a0 = p1, a1 = p2, a2 = zp;
            #pragma unroll
            for (int o = 16; o; o >>= 1) {
                a0 += __shfl_xor_sync(0xffffffffu, a0, o);
                a1 += __shfl_xor_sync(0xffffffffu, a1, o);
                a2 += __shfl_xor_sync(0xffffffffu, a2, o);
            }
            if (lane == 0) {
                warpRed[wid]      = a0;
                warpRed[8 + wid]  = a1;
                warpRed[16 + wid] = a2;
            }
            __syncthreads();
            if (tid == 0) {
                float m1 = 0.0f, m2 = 0.0f, zz = 0.0f;
                #pragma unroll
                for (int i = 0; i < 8; i++) {
                    m1 += warpRed[i];
                    m2 += warpRed[8 + i];
                    zz += warpRed[16 + i];
                }
                if (it == 0) s_ctl[3] = zz;           // Z
                float T = 0.8f * s_ctl[3];
                if (m1 >= T)      { s_ctl[0] = lo; s_ctl[1] = t1; s_ctl[2] = mLo; }
                else if (m2 >= T) { s_ctl[0] = t1; s_ctl[1] = t2; s_ctl[2] = m1;  }
                else              { s_ctl[0] = t2; s_ctl[1] = hi; s_ctl[2] = m2;  }
            }
            __syncthreads();
            lo  = s_ctl[0];
            hi  = s_ctl[1];
            mLo = s_ctl[2];
            Z   = s_ctl[3];
            zp  = 0.0f;
        }
        const float T    = 0.8f * Z;
        const float eThr = 1e-10f * Z;                 // p > THRESHOLD filter

        // ---- final pass: accumulate surely-kept, collect boundary candidates ----
        float acc = 0.0f;
        #pragma unroll
        for (int k = 0; k < NPT; k++) {
            float2 v = de[k * NTHREADS + tid];
            if (v.x < lo) {
                if (v.y > eThr) acc = fmaf(v.y, v.x, acc);
            } else if (v.x < hi) {
                int idx = atomicAdd(&s_cnt, 1);
                if (idx < CAP) { listD[idx] = v.x; listE[idx] = v.y; }
                else if (v.y > eThr) acc = fmaf(v.y, v.x, acc);  // ~impossible
            }
        }
        __syncthreads();

        // ---- exact rank resolution in [lo, hi) ----
        const int   cnt  = s_cnt < CAP ? s_cnt : CAP;
        const float Trem = T - mLo;
        for (int i = tid; i < cnt; i += NTHREADS) {
            float di = listD[i];
            float ei = listE[i];
            float rm = 0.0f;
            for (int j = 0; j < cnt; j++) {
                float dj = listD[j];
                rm += ((dj < di) || (dj == di && j < i)) ? listE[j] : 0.0f;
            }
            if (rm < Trem && ei > eThr) acc = fmaf(ei, di, acc);
        }

        // ---- block reduce row contribution ----
        #pragma unroll
        for (int o = 16; o; o >>= 1)
            acc += __shfl_xor_sync(0xffffffffu, acc, o);
        if (lane == 0) warpRed[wid] = acc;
        __syncthreads();
        if (tid == 0) {
            float tot = 0.0f;
            #pragma unroll
            for (int i = 0; i < 8; i++) tot += warpRed[i];
            ctaAcc += tot / Z;
        }
        __syncthreads();   // protect smem before next row reuses de/s_cnt
    }

    if (tid == 0) atomicAdd(out, ctaAcc);
}

extern "C" void kernel_launch(void* const* d_in, const int* in_sizes, int n_in,
                              void* d_out, int out_size)
{
    const float* x = (const float*)d_in[0];
    const float* y = (const float*)d_in[1];
    float* out = (float*)d_out;

    apml_zero_out<<<1, 1>>>(out);
    const int grid = (4 * MPTS) / RPC;   // 2048 CTAs
    apml_kernel<<<grid, NTHREADS>>>(x, y, out);
}

// round 4
// speedup vs baseline: 1.3919x; 1.3919x over previous
#include <cuda_runtime.h>

// APMLSparse: x[B,N,3], y[B,M,3] fp32 -> scalar loss. B=4, N=M=4096.
// Per row: d_j = sqrt(max(||x-y_j||^2,1e-12)), e_j=exp(-d_j), Z=sum e_j.
// Kept = d-ascending prefix while exclusive cumulative mass < 0.8*Z (incl.
// crossing entry, p>1e-10 filter). loss += sum_kept e_j*d_j / Z.
//
// R3: single full-data octasection (7 thresholds, register-resident d) to
// bracket the weighted-quantile threshold, warp-aggregated compaction of the
// ~1e3 boundary-band elements to smem, two penta-section rounds on that list,
// exact O(k^2) resolution of the ~60 survivors. 512-thread CTAs, 2/SM.

#define NTH   512
#define NPT   8            // 4096 / NTH
#define RPC   8
#define MPTS  4096
#define CAP   3072
#define CAP2  256

__global__ void apml_zero_out(float* o){ o[0] = 0.0f; }

__device__ __forceinline__ float wredSum(float v){
#pragma unroll
    for (int o = 16; o; o >>= 1) v += __shfl_xor_sync(0xffffffffu, v, o);
    return v;
}

__global__ __launch_bounds__(NTH, 2)
void apml_kernel(const float* __restrict__ x, const float* __restrict__ y,
                 float* __restrict__ out)
{
    __shared__ float  eArr[MPTS];        // 16 KB
    __shared__ float2 list[CAP];         // 24 KB
    __shared__ float  l2d[CAP2];         // 1 KB
    __shared__ float  l2e[CAP2];         // 1 KB
    __shared__ float  warpRed[7 * 16];
    __shared__ float  s_m[8];
    __shared__ int    s_cnt, s_cnt2;

    const int tid = threadIdx.x, lane = tid & 31, wid = tid >> 5;
    const int cpb = MPTS / RPC;                   // 512
    const int b = blockIdx.x / cpb;
    const int rowBase = (blockIdx.x % cpb) * RPC;

    // 8 y-points per thread in registers, reused across RPC rows.
    float yx[NPT], yy[NPT], yz[NPT];
    const float* yb = y + (size_t)b * MPTS * 3;
#pragma unroll
    for (int k = 0; k < NPT; k++) {
        int j = k * NTH + tid;
        yx[k] = yb[j * 3 + 0];
        yy[k] = yb[j * 3 + 1];
        yz[k] = yb[j * 3 + 2];
    }

    float ctaAcc = 0.0f;

    for (int r = 0; r < RPC; r++) {
        const float* xp = x + ((size_t)b * MPTS + rowBase + r) * 3;
        const float x0 = __ldg(xp + 0);
        const float x1 = __ldg(xp + 1);
        const float x2 = __ldg(xp + 2);

        if (tid == 0) { s_cnt = 0; s_cnt2 = 0; }

        // ---- pass 1: d -> regs, e -> smem; reduce Z, dmin, dmax ----
        float dreg[NPT];
        float z = 0.0f, dmn = 1e30f, dmx = -1e30f;
#pragma unroll
        for (int k = 0; k < NPT; k++) {
            float dx = x0 - yx[k];
            float dy = x1 - yy[k];
            float dz = x2 - yz[k];
            float sq = fmaf(dx, dx, fmaf(dy, dy, dz * dz));
            sq = fmaxf(sq, 1e-12f);
            float d = sq * rsqrtf(sq);        // sqrt via MUFU.RSQ + FMUL
            dreg[k] = d;
            float e = __expf(-d);
            eArr[k * NTH + tid] = e;
            z += e;
            dmn = fminf(dmn, d);
            dmx = fmaxf(dmx, d);
        }
        z = wredSum(z);
#pragma unroll
        for (int o = 16; o; o >>= 1) {
            dmn = fminf(dmn, __shfl_xor_sync(0xffffffffu, dmn, o));
            dmx = fmaxf(dmx, __shfl_xor_sync(0xffffffffu, dmx, o));
        }
        if (lane == 0) { warpRed[wid] = z; warpRed[16 + wid] = dmn; warpRed[32 + wid] = dmx; }
        __syncthreads();
        if (wid == 0) {
            float v = (lane < 16) ? warpRed[lane] : 0.0f;
#pragma unroll
            for (int o = 8; o; o >>= 1) v += __shfl_xor_sync(0xffffffffu, v, o);
            if (lane == 0) s_m[0] = v;
        } else if (wid == 1) {
            float v = (lane < 16) ? warpRed[16 + lane] : 1e30f;
#pragma unroll
            for (int o = 8; o; o >>= 1) v = fminf(v, __shfl_xor_sync(0xffffffffu, v, o));
            if (lane == 0) s_m[1] = v;
        } else if (wid == 2) {
            float v = (lane < 16) ? warpRed[32 + lane] : -1e30f;
#pragma unroll
            for (int o = 8; o; o >>= 1) v = fmaxf(v, __shfl_xor_sync(0xffffffffu, v, o));
            if (lane == 0) s_m[2] = v;
        }
        __syncthreads();
        const float Z    = s_m[0];
        const float l0   = s_m[1];
        const float dmax = s_m[2];
        const float h0   = dmax + fmaxf(dmax * 1e-5f, 1e-6f);   // strictly above all d
        const float T    = 0.8f * Z;
        const float eThr = 1e-10f * Z;
        const float w8   = (h0 - l0) * 0.125f;

        // ---- round 1: octasection over register-resident d ----
        float m0=0,m1=0,m2=0,m3=0,m4=0,m5=0,m6=0;
        const float t1=l0+w8, t2=l0+2.f*w8, t3=l0+3.f*w8, t4=l0+4.f*w8,
                    t5=l0+5.f*w8, t6=l0+6.f*w8, t7=l0+7.f*w8;
#pragma unroll
        for (int k = 0; k < NPT; k++) {
            float d = dreg[k];
            float e = eArr[k * NTH + tid];
            m0 += (d < t1) ? e : 0.f;  m1 += (d < t2) ? e : 0.f;
            m2 += (d < t3) ? e : 0.f;  m3 += (d < t4) ? e : 0.f;
            m4 += (d < t5) ? e : 0.f;  m5 += (d < t6) ? e : 0.f;
            m6 += (d < t7) ? e : 0.f;
        }
        m0=wredSum(m0); m1=wredSum(m1); m2=wredSum(m2); m3=wredSum(m3);
        m4=wredSum(m4); m5=wredSum(m5); m6=wredSum(m6);
        if (lane == 0) {
            warpRed[0*16+wid]=m0; warpRed[1*16+wid]=m1; warpRed[2*16+wid]=m2;
            warpRed[3*16+wid]=m3; warpRed[4*16+wid]=m4; warpRed[5*16+wid]=m5;
            warpRed[6*16+wid]=m6;
        }
        __syncthreads();
        if (wid < 7) {
            float v = (lane < 16) ? warpRed[wid * 16 + lane] : 0.0f;
#pragma unroll
            for (int o = 8; o; o >>= 1) v += __shfl_xor_sync(0xffffffffu, v, o);
            if (lane == 0) s_m[wid] = v;
        }
        __syncthreads();

        // pick bracket [l,h) with mass(l) < T <= mass(h)  (identical on all threads)
        float l = l0, h = h0, mLo = 0.0f;
        {
            bool found = false;
#pragma unroll
            for (int i = 0; i < 7; i++) {
                float ti = l0 + (float)(i + 1) * w8;
                if (!found) {
                    if (s_m[i] >= T) { h = ti; found = true; }
                    else             { l = ti; mLo = s_m[i]; }
                }
            }
        }
        const float mLo0  = mLo;   // mass strictly below list's lower edge
        const float lList = l, hList = h;

        // ---- compact boundary band to smem (warp-aggregated append) ----
        float acc = 0.0f;
#pragma unroll
        for (int k = 0; k < NPT; k++) {
            float d = dreg[k];
            float e = eArr[k * NTH + tid];
            bool kept = d < lList;
            bool cand = (!kept) && (d < hList);
            if (kept && e > eThr) acc = fmaf(e, d, acc);
            unsigned mk = __ballot_sync(0xffffffffu, cand);
            if (mk) {
                int leader = __ffs(mk) - 1;
                int base = 0;
                if (lane == leader) base = atomicAdd(&s_cnt, __popc(mk));
                base = __shfl_sync(0xffffffffu, base, leader);
                if (cand) {
                    int idx = base + __popc(mk & ((1u << lane) - 1u));
                    if (idx < CAP) list[idx] = make_float2(d, e);
                    else if (e > eThr) acc = fmaf(e, d, acc);   // overflow fallback
                }
            }
        }
        __syncthreads();
        const int cnt = s_cnt < CAP ? s_cnt : CAP;

        // ---- two penta-section rounds on the list ----
        float mLoCur = mLo0;
#pragma unroll
        for (int rd = 0; rd < 2; rd++) {
            float w5 = (h - l) * 0.2f;
            float u1 = l + w5, u2 = l + 2.f*w5, u3 = l + 3.f*w5, u4 = l + 4.f*w5;
            float p0 = 0, p1 = 0, p2 = 0, p3 = 0;
            for (int i = tid; i < cnt; i += NTH) {
                float2 v = list[i];
                p0 += (v.x < u1) ? v.y : 0.f;
                p1 += (v.x < u2) ? v.y : 0.f;
                p2 += (v.x < u3) ? v.y : 0.f;
                p3 += (v.x < u4) ? v.y : 0.f;
            }
            p0 = wredSum(p0); p1 = wredSum(p1); p2 = wredSum(p2); p3 = wredSum(p3);
            if (lane == 0) {
                warpRed[0*16+wid] = p0; warpRed[1*16+wid] = p1;
                warpRed[2*16+wid] = p2; warpRed[3*16+wid] = p3;
            }
            __syncthreads();
            if (wid < 4) {
                float v = (lane < 16) ? warpRed[wid * 16 + lane] : 0.0f;
#pragma unroll
                for (int o = 8; o; o >>= 1) v += __shfl_xor_sync(0xffffffffu, v, o);
                if (lane == 0) s_m[wid] = v;
            }
            __syncthreads();
            bool found = false;
            float nl = l, nh = h, nm = mLoCur;
#pragma unroll
            for (int i = 0; i < 4; i++) {
                float ui = l + (float)(i + 1) * w5;
                float mg = mLo0 + s_m[i];      // global mass below ui
                if (!found) {
                    if (mg >= T) { nh = ui; found = true; }
                    else         { nl = ui; nm = mg; }
                }
            }
            l = nl; h = nh; mLoCur = nm;
            __syncthreads();                   // s_m stable before next round's rewrite
        }

        // ---- recompact final band, exact O(k^2) rank resolution ----
        for (int i = tid; i < cnt; i += NTH) {
            float2 v = list[i];
            if (v.x < l) {
                if (v.y > eThr) acc = fmaf(v.y, v.x, acc);
            } else if (v.x < h) {
                int idx = atomicAdd(&s_cnt2, 1);
                if (idx < CAP2) { l2d[idx] = v.x; l2e[idx] = v.y; }
                else if (v.y > eThr) acc = fmaf(v.y, v.x, acc);
            }
        }
        __syncthreads();
        const int c2 = s_cnt2 < CAP2 ? s_cnt2 : CAP2;
        const float Trem = T - mLoCur;
        for (int i = tid; i < c2; i += NTH) {
            float di = l2d[i], ei = l2e[i], rm = 0.0f;
            for (int j = 0; j < c2; j++) {
                float dj = l2d[j];
                rm += ((dj < di) || (dj == di && j < i)) ? l2e[j] : 0.0f;
            }
            if (rm < Trem && ei > eThr) acc = fmaf(ei, di, acc);
        }

        // ---- row reduce ----
        acc = wredSum(acc);
        if (lane == 0) warpRed[wid] = acc;
        __syncthreads();
        if (tid == 0) {
            float tot = 0.0f;
#pragma unroll
            for (int i = 0; i < 16; i++) tot += warpRed[i];
            ctaAcc += tot / Z;
        }
        __syncthreads();   // protect smem before next row
    }

    if (tid == 0) atomicAdd(out, ctaAcc);
}

extern "C" void kernel_launch(void* const* d_in, const int* in_sizes, int n_in,
                              void* d_out, int out_size)
{
    const float* x = (const float*)d_in[0];
    const float* y = (const float*)d_in[1];
    float* out = (float*)d_out;

    apml_zero_out<<<1, 1>>>(out);
    const int grid = (4 * MPTS) / RPC;   // 2048 CTAs
    apml_kernel<<<grid, NTH>>>(x, y, out);
}

// round 6
// speedup vs baseline: 2.2757x; 1.6350x over previous
#include <cuda_runtime.h>

// APMLSparse: x[B,N,3], y[B,M,3] fp32 -> scalar loss. B=4, N=M=4096.
// Per row: d_j = sqrt(max(||x-y_j||^2,1e-12)), e_j=exp(-d_j), Z=sum e_j.
// Kept = d-ascending prefix while exclusive cumulative mass < 0.8*Z (incl.
// crossing entry). loss += sum_kept e_j*d_j / Z.
//
// R4: threshold search via per-THREAD-private banked smem histograms (zero
// atomics, conflict-free: addr = bin*NTH+tid). Two 16-bin stages over fixed
// [0,16] (stage 1 fused into the distance pass) -> crossing window width 1/16
// (~110 elems) -> one penta round -> ~25 survivors -> exact O(k^2) rank
// resolution. d kept in registers (NPT=8); e recomputed from d where needed.

#define NTH   512
#define NPT   8            // 4096 / NTH
#define RPC   8
#define MPTS  4096
#define NB    16           // bins per stage
#define HISTN (NB * NTH)   // 8192 floats = 32 KB
#define CAP   512
#define CAP2  128

__global__ void apml_zero_out(float* o) { o[0] = 0.0f; }

__global__ __launch_bounds__(NTH, 2)
void apml_kernel(const float* __restrict__ x, const float* __restrict__ y,
                 float* __restrict__ out)
{
    __shared__ float  hist[HISTN];      // 32 KB private histogram columns
    __shared__ float2 list[CAP];        // 4 KB crossing-window elements
    __shared__ float  l2d[CAP2];        // final band
    __shared__ float  l2e[CAP2];
    __shared__ float  binTot[NB];
    __shared__ float  warpRed[64];
    __shared__ float  s_ctl[8];         // 0:Z 1:T 2:(c1|l2f) 3:h2f 4:mLo 5:l3 6:h3 7:mLo3
    __shared__ int    s_int[2];

    const int tid  = threadIdx.x, lane = tid & 31, wid = tid >> 5;
    const int cpb  = MPTS / RPC;                    // 512
    const int b    = blockIdx.x / cpb;
    const int rowBase = (blockIdx.x % cpb) * RPC;

    // 8 y-points per thread in registers, reused across RPC rows.
    float yx[NPT], yy[NPT], yz[NPT];
    const float* yb = y + (size_t)b * MPTS * 3;
#pragma unroll
    for (int k = 0; k < NPT; k++) {
        int j = k * NTH + tid;
        yx[k] = yb[j * 3 + 0];
        yy[k] = yb[j * 3 + 1];
        yz[k] = yb[j * 3 + 2];
    }

    float4* hist4 = (float4*)hist;
    float ctaAcc = 0.0f;

    for (int r = 0; r < RPC; r++) {
        const float* xp = x + ((size_t)b * MPTS + rowBase + r) * 3;
        const float x0 = __ldg(xp + 0);
        const float x1 = __ldg(xp + 1);
        const float x2 = __ldg(xp + 2);

        // ---- zero histogram (float4) ----
#pragma unroll
        for (int i = 0; i < HISTN / 4 / NTH; i++)
            hist4[tid + i * NTH] = make_float4(0.f, 0.f, 0.f, 0.f);
        if (tid == 0) { s_int[0] = 0; s_int[1] = 0; }
        __syncthreads();

        // ---- pass 1 fused with stage-1 fill: bins of width 1 over [0,16) ----
        float dreg[NPT];
#pragma unroll
        for (int k = 0; k < NPT; k++) {
            float dx = x0 - yx[k];
            float dy = x1 - yy[k];
            float dz = x2 - yz[k];
            float sq = fmaf(dx, dx, fmaf(dy, dy, dz * dz));
            sq = fmaxf(sq, 1e-12f);
            float d = sq * rsqrtf(sq);              // sqrt via MUFU.RSQ + FMUL
            dreg[k] = d;
            float e = __expf(-d);
            int bin = (int)d;
            bin = bin < (NB - 1) ? bin : (NB - 1);  // clamp stray large d
            hist[bin * NTH + tid] += e;             // conflict-free column
        }
        __syncthreads();

        // ---- stage-1 reduce: warp w sums bin w via float4 ----
        {
            float s = 0.f;
            int base = wid * (NTH / 4);
#pragma unroll
            for (int i = 0; i < NTH / 4 / 32; i++) {
                float4 v = hist4[base + lane + i * 32];
                s += (v.x + v.y) + (v.z + v.w);
            }
#pragma unroll
            for (int o = 16; o; o >>= 1) s += __shfl_xor_sync(0xffffffffu, s, o);
            if (lane == 0) binTot[wid] = s;
        }
        __syncthreads();

        // ---- stage-1 scan + pick (warp 0): Z, T, crossing bin c1, mLo1 ----
        if (wid == 0) {
            float mm = (lane < NB) ? binTot[lane] : 0.f;
            float incl = mm;
#pragma unroll
            for (int o = 1; o < NB; o <<= 1) {
                float t = __shfl_up_sync(0xffffffffu, incl, o);
                if (lane >= o) incl += t;
            }
            float total = __shfl_sync(0xffffffffu, incl, NB - 1);
            float T = 0.8f * total;
            float excl = incl - mm;
            bool cross = (lane < NB) && (excl < T) && (incl >= T);
            unsigned bal = __ballot_sync(0xffffffffu, cross);
            int c1 = bal ? (__ffs(bal) - 1) : (NB - 1);
            float mlo = __shfl_sync(0xffffffffu, excl, c1);
            if (lane == 0) {
                s_ctl[0] = total;            // Z
                s_ctl[1] = T;
                s_ctl[2] = (float)c1;
                s_ctl[4] = mlo;              // mLo1
            }
        }
        __syncthreads();
        const float Z    = s_ctl[0];
        const float T    = s_ctl[1];
        const int   c1s  = ((int)s_ctl[2]) << 4;    // c1*16
        const float mLo1 = s_ctl[4];

        // ---- zero histogram for stage 2 ----
#pragma unroll
        for (int i = 0; i < HISTN / 4 / NTH; i++)
            hist4[tid + i * NTH] = make_float4(0.f, 0.f, 0.f, 0.f);
        __syncthreads();

        // ---- stage-2 fill: 16 sub-bins of width 1/16 over crossing bin ----
#pragma unroll
        for (int k = 0; k < NPT; k++) {
            float d = dreg[k];
            int b2 = (int)(d * 16.0f) - c1s;        // exact: x16 is 2^4 scale
            if ((unsigned)b2 < (unsigned)NB) {
                float e = __expf(-d);
                hist[b2 * NTH + tid] += e;
            }
        }
        __syncthreads();

        // ---- stage-2 reduce ----
        {
            float s = 0.f;
            int base = wid * (NTH / 4);
#pragma unroll
            for (int i = 0; i < NTH / 4 / 32; i++) {
                float4 v = hist4[base + lane + i * 32];
                s += (v.x + v.y) + (v.z + v.w);
            }
#pragma unroll
            for (int o = 16; o; o >>= 1) s += __shfl_xor_sync(0xffffffffu, s, o);
            if (lane == 0) binTot[wid] = s;
        }
        __syncthreads();

        // ---- stage-2 scan + pick ----
        if (wid == 0) {
            float mm = (lane < NB) ? binTot[lane] : 0.f;
            float incl = mm;
#pragma unroll
            for (int o = 1; o < NB; o <<= 1) {
                float t = __shfl_up_sync(0xffffffffu, incl, o);
                if (lane >= o) incl += t;
            }
            float excl = incl - mm;
            bool cross = (lane < NB) && (mLo1 + excl < T) && (mLo1 + incl >= T);
            unsigned bal = __ballot_sync(0xffffffffu, cross);
            int c2 = bal ? (__ffs(bal) - 1) : (NB - 1);   // fp-mismatch fallback
            float mlo2 = mLo1 + __shfl_sync(0xffffffffu, excl, c2);
            if (lane == 0) {
                float l2f = (float)(c1s + c2) * 0.0625f;  // exact fp
                s_ctl[2] = l2f;
                s_ctl[3] = l2f + 0.0625f;
                s_ctl[4] = mlo2;
            }
        }
        __syncthreads();
        const float l2f  = s_ctl[2];
        const float h2f  = s_ctl[3];
        const float mLo2 = s_ctl[4];

        // ---- compact crossing window + accumulate surely-kept sum ----
        float acc = 0.0f;
#pragma unroll
        for (int k = 0; k < NPT; k++) {
            float d = dreg[k];
            bool kept = d < l2f;
            bool band = (!kept) && (d < h2f);
            if (kept) acc = fmaf(__expf(-d), d, acc);
            unsigned mk = __ballot_sync(0xffffffffu, band);
            if (mk) {
                int leader = __ffs(mk) - 1;
                int base2 = 0;
                if (lane == leader) base2 = atomicAdd(&s_int[0], __popc(mk));
                base2 = __shfl_sync(0xffffffffu, base2, leader);
                if (band) {
                    int idx = base2 + __popc(mk & ((1u << lane) - 1u));
                    float e = __expf(-d);
                    if (idx < CAP) list[idx] = make_float2(d, e);
                    else           acc = fmaf(e, d, acc);  // overflow fallback
                }
            }
        }
        __syncthreads();
        const int cnt = s_int[0] < CAP ? s_int[0] : CAP;

        // ---- one penta round on the ~110-element list ----
        {
            float w  = (h2f - l2f) * 0.2f;
            float u1 = l2f + w, u2 = l2f + 2.f * w, u3 = l2f + 3.f * w, u4 = l2f + 4.f * w;
            float p0 = 0.f, p1 = 0.f, p2 = 0.f, p3 = 0.f;
            for (int i = tid; i < cnt; i += NTH) {
                float2 v = list[i];
                p0 += (v.x < u1) ? v.y : 0.f;
                p1 += (v.x < u2) ? v.y : 0.f;
                p2 += (v.x < u3) ? v.y : 0.f;
                p3 += (v.x < u4) ? v.y : 0.f;
            }
#pragma unroll
            for (int o = 16; o; o >>= 1) {
                p0 += __shfl_xor_sync(0xffffffffu, p0, o);
                p1 += __shfl_xor_sync(0xffffffffu, p1, o);
                p2 += __shfl_xor_sync(0xffffffffu, p2, o);
                p3 += __shfl_xor_sync(0xffffffffu, p3, o);
            }
            if (lane == 0) {
                warpRed[wid] = p0; warpRed[16 + wid] = p1;
                warpRed[32 + wid] = p2; warpRed[48 + wid] = p3;
            }
            __syncthreads();
            if (wid == 0) {
                float s = 0.f;
                if (lane < 4) {
#pragma unroll
                    for (int i = 0; i < 16; i++) s += warpRed[lane * 16 + i];
                }
                float m1 = __shfl_sync(0xffffffffu, s, 0);
                float m2 = __shfl_sync(0xffffffffu, s, 1);
                float m3 = __shfl_sync(0xffffffffu, s, 2);
                float m4 = __shfl_sync(0xffffffffu, s, 3);
                if (lane == 0) {
                    float l = l2f, h = u1, ml = mLo2;
                    if (mLo2 + m1 < T) { l = u1; h = u2; ml = mLo2 + m1;
                      if (mLo2 + m2 < T) { l = u2; h = u3; ml = mLo2 + m2;
                        if (mLo2 + m3 < T) { l = u3; h = u4; ml = mLo2 + m3;
                          if (mLo2 + m4 < T) { l = u4; h = h2f; ml = mLo2 + m4; } } } }
                    s_ctl[5] = l; s_ctl[6] = h; s_ctl[7] = ml;
                }
            }
            __syncthreads();
        }
        const float l3 = s_ctl[5], h3 = s_ctl[6], mLo3 = s_ctl[7];

        // ---- recompact final band ----
        for (int i = tid; i < cnt; i += NTH) {
            float2 v = list[i];
            if (v.x < l3) {
                acc = fmaf(v.y, v.x, acc);
            } else if (v.x < h3) {
                int idx = atomicAdd(&s_int[1], 1);
                if (idx < CAP2) { l2d[idx] = v.x; l2e[idx] = v.y; }
                else            acc = fmaf(v.y, v.x, acc);
            }
        }
        __syncthreads();

        // ---- exact O(k^2) rank resolution (crossing-entry semantics) ----
        const int   c2n  = s_int[1] < CAP2 ? s_int[1] : CAP2;
        const float Trem = T - mLo3;
        for (int i = tid; i < c2n; i += NTH) {
            float di = l2d[i], ei = l2e[i], rm = 0.f;
            for (int j = 0; j < c2n; j++) {
                float dj = l2d[j];
                rm += ((dj < di) || (dj == di && j < i)) ? l2e[j] : 0.f;
            }
            if (rm < Trem) acc = fmaf(ei, di, acc);
        }

        // ---- row reduce ----
#pragma unroll
        for (int o = 16; o; o >>= 1) acc += __shfl_xor_sync(0xffffffffu, acc, o);
        if (lane == 0) warpRed[wid] = acc;
        __syncthreads();
        if (tid == 0) {
            float tot = 0.f;
#pragma unroll
            for (int i = 0; i < 16; i++) tot += warpRed[i];
            ctaAcc += tot / Z;
        }
        __syncthreads();   // protect smem before next row's zeroing
    }

    if (tid == 0) atomicAdd(out, ctaAcc);
}

extern "C" void kernel_launch(void* const* d_in, const int* in_sizes, int n_in,
                              void* d_out, int out_size)
{
    const float* x = (const float*)d_in[0];
    const float* y = (const float*)d_in[1];
    float* out = (float*)d_out;

    apml_zero_out<<<1, 1>>>(out);
    const int grid = (4 * MPTS) / RPC;   // 2048 CTAs
    apml_kernel<<<grid, NTH>>>(x, y, out);
}